// round 9
// baseline (speedup 1.0000x reference)
#include <cuda_runtime.h>
#include <math.h>

#define NB      8192
#define ND      512
#define NK      8
#define FULL    0xffffffffu

#define THREADS 256
#define WARPS   8
#define GRID    512          // 512 blocks * 4/SM cap <= 592 resident -> barrier safe
#define RANKBLK 256          // blocks participating in rank phase
#define RROWS   4            // rows ranked per warp

__device__ double             g_acc;
__device__ int                g_done = 0;
__device__ int                g_bar  = 0;
__device__ unsigned long long g_keys[NB];
__device__ float              g_slab[NB];   // labels in sorted order
__device__ int                g_sidx[NB];   // original row per sorted position

// grid-wide barrier: monotonic arrive counter, reset by the finalizing block
__device__ __forceinline__ void grid_barrier(int target)
{
    __syncthreads();
    if (threadIdx.x == 0) {
        __threadfence();
        atomicAdd(&g_bar, 1);
        while (*((volatile int*)&g_bar) < target) { }
    }
    __syncthreads();
}

__global__ void __launch_bounds__(THREADS, 4) nest_fused_kernel(
    const float* __restrict__ S,   // [NB, ND]
    const float* __restrict__ L,   // [NB]
    float* __restrict__ out)
{
    __shared__ float sSim[WARPS];

    const int tid  = threadIdx.x;
    const int wid  = tid >> 5;
    const int lane = tid & 31;
    const int bid  = blockIdx.x;

    // ---------------- Phase 0: build unique 64-bit sort keys ----------------
    // key = label_bits<<13 | idx : labels nonneg -> uint order == float order;
    // idx makes keys unique, so ranks form an exact permutation.
    {
        int i = bid * THREADS + tid;
        if (i < NB)
            g_keys[i] = ((unsigned long long)__float_as_uint(L[i]) << 13) | (unsigned)i;
        if (i == 0) g_acc = 0.0;
    }

    grid_barrier(GRID);

    // ---------------- Phase 1: counting rank, 4 rows per warp ----------------
    if (bid < RANKBLK) {
        const int base = (bid * WARPS + wid) * RROWS;

        unsigned long long kb[RROWS];
        int rr[RROWS];
#pragma unroll
        for (int j = 0; j < RROWS; j++) { kb[j] = g_keys[base + j]; rr[j] = 0; }

        const ulonglong2* K2 = (const ulonglong2*)g_keys;
#pragma unroll 4
        for (int c = lane; c < NB / 2; c += 32) {
            ulonglong2 kk = K2[c];
#pragma unroll
            for (int j = 0; j < RROWS; j++) {
                rr[j] += (kk.x < kb[j]);
                rr[j] += (kk.y < kb[j]);
            }
        }

#pragma unroll
        for (int j = 0; j < RROWS; j++) {
#pragma unroll
            for (int off = 16; off > 0; off >>= 1)
                rr[j] += __shfl_xor_sync(FULL, rr[j], off);
        }

        if (lane == 0) {
#pragma unroll
            for (int j = 0; j < RROWS; j++) {
                g_slab[rr[j]] = __uint_as_float((unsigned)(kb[j] >> 13));
                g_sidx[rr[j]] = base + j;
            }
        }
    }

    grid_barrier(2 * GRID);

    // ---------------- Phase 2: main — warp per sorted row, 2 rows/warp -------
    float mySim = 0.0f;
    const int r0 = (bid * WARPS + wid) * 2;

#pragma unroll
    for (int rr2 = 0; rr2 < 2; rr2++) {
        const int r = r0 + rr2;

        // --- parallel window select: lanes 0..14 hold candidates r-7..r+7 ---
        int  p     = r - 7 + lane;
        bool valid = (lane < 15) && (p >= 0) && (p < NB);
        float lab  = valid ? g_slab[p] : 0.0f;
        int   gi   = valid ? g_sidx[p] : 0;

        float Lb = __shfl_sync(FULL, lab, 7);           // lane 7 == self (p==r)
        float d  = valid ? fabsf(lab - Lb) : INFINITY;  // lanes >=15 excluded

        int rank = 0;
#pragma unroll
        for (int src = 0; src < 15; src++) {
            float od = __shfl_sync(FULL, d, src);
            rank += (od < d) | ((od == d) & (src < lane));   // unique ranks
        }
        bool sel = (rank < NK) && (lane < 15);

        float e = sel ? __expf(-d * d * (1.0f / 50.0f)) : 0.0f;  // 2*STD^2 = 50
        float wsum = e;
#pragma unroll
        for (int off = 16; off > 0; off >>= 1)
            wsum += __shfl_xor_sync(FULL, wsum, off);
        const float winv = 1.0f / wsum;

        int   gidx[NK];
        float w[NK];
#pragma unroll
        for (int k = 0; k < NK; k++) {
            unsigned m  = __ballot_sync(FULL, sel && (rank == k));
            int      sl = __ffs(m) - 1;
            gidx[k] = __shfl_sync(FULL, gi, sl);
            w[k]    = __shfl_sync(FULL, e,  sl) * winv;
        }
        const int b = __shfl_sync(FULL, gi, 7);         // original self row

        // --- fused gather + weighted mean + cosine terms ---
        const float4* xr = (const float4*)(S + (size_t)b * ND);
        float dot = 0.0f, nx = 0.0f, nm = 0.0f;

#pragma unroll
        for (int t = 0; t < 4; t++) {
            int col = lane + t * 32;
            float4 x = xr[col];
            float mx = 0.0f, my = 0.0f, mz = 0.0f, mw = 0.0f;
#pragma unroll
            for (int k = 0; k < NK; k++) {
                float4 s = ((const float4*)(S + (size_t)gidx[k] * ND))[col];
                mx = fmaf(w[k], s.x, mx);
                my = fmaf(w[k], s.y, my);
                mz = fmaf(w[k], s.z, mz);
                mw = fmaf(w[k], s.w, mw);
            }
            dot += x.x * mx + x.y * my + x.z * mz + x.w * mw;
            nx  += x.x * x.x + x.y * x.y + x.z * x.z + x.w * x.w;
            nm  += mx * mx + my * my + mz * mz + mw * mw;
        }

#pragma unroll
        for (int off = 16; off > 0; off >>= 1) {
            dot += __shfl_xor_sync(FULL, dot, off);
            nx  += __shfl_xor_sync(FULL, nx,  off);
            nm  += __shfl_xor_sync(FULL, nm,  off);
        }

        if (lane == 0)
            mySim += dot / ((1e-10f + sqrtf(nx)) * (1e-10f + sqrtf(nm)));
    }

    if (lane == 0) sSim[wid] = mySim;
    __syncthreads();

    // ---------------- block reduce + last-block finalize ----------------
    if (tid == 0) {
        double bs = 0.0;
#pragma unroll
        for (int k = 0; k < WARPS; k++) bs += (double)sSim[k];
        atomicAdd(&g_acc, bs);
        __threadfence();
        int old = atomicAdd(&g_done, 1);
        if (old == GRID - 1) {
            double total = *((volatile double*)&g_acc);
            out[0] = (float)(1.0 - total / (double)NB);
            g_done = 0;            // reset counters for next graph replay
            g_bar  = 0;
        }
    }
}

extern "C" void kernel_launch(void* const* d_in, const int* in_sizes, int n_in,
                              void* d_out, int out_size)
{
    const float* S = (const float*)d_in[0];   // Struct [8192, 512]
    const float* L = (const float*)d_in[1];   // Label  [8192]
    float* out = (float*)d_out;

    nest_fused_kernel<<<GRID, THREADS>>>(S, L, out);
}

// round 11
// speedup vs baseline: 1.8661x; 1.8661x over previous
#include <cuda_runtime.h>
#include <math.h>

#define NB    8192
#define ND    512
#define NDF4  (ND / 4)        // 128 float4 per row
#define NK    8
#define FULL  0xffffffffu

// ---- main (stencil) kernel geometry ----
#define TOUT   32                      // output sorted rows per block
#define HALO   7
#define STAGE  (TOUT + 2 * HALO)       // 46 staged rows
#define MT     256
#define MWARPS 8
#define MBLK   (NB / TOUT)             // 256 blocks

// dynamic smem partition (bytes)
#define OFF_SS   0
#define OFF_SW   (STAGE * NDF4 * 16)           // 94208
#define OFF_RED  (OFF_SW + TOUT * 16 * 4)      // 96256
#define OFF_SRC  (OFF_RED + 8 * 8 * 4 * 4)     // 97280
#define SMEM_SZ  (OFF_SRC + 192)               // 97472

// ---- rank kernel geometry (R8, known good) ----
#define RT     128
#define RROWS  8
#define RWARPS (RT / 32)
#define RBLK   (NB / (RROWS * RWARPS))  // 256

__device__ double g_acc;
__device__ int    g_done = 0;
__device__ float  g_slab[NB];   // labels in sorted order
__device__ int    g_sidx[NB];   // original row per sorted position

// ---------------- Rank kernel: warp per 8 rows, counting rank ---------------
__global__ void __launch_bounds__(RT) nest_rank_kernel(const float* __restrict__ L)
{
    __shared__ unsigned long long sK[NB];   // 64 KB

    const int tid  = threadIdx.x;
    const int wid  = tid >> 5;
    const int lane = tid & 31;

    if (blockIdx.x == 0 && tid == 0) g_acc = 0.0;

    for (int i = tid; i < NB; i += RT)
        sK[i] = ((unsigned long long)__float_as_uint(L[i]) << 13) | (unsigned)i;
    __syncthreads();

    const int base = (blockIdx.x * RWARPS + wid) * RROWS;

    unsigned long long kb[RROWS];
    int rr[RROWS];
#pragma unroll
    for (int j = 0; j < RROWS; j++) { kb[j] = sK[base + j]; rr[j] = 0; }

#pragma unroll 4
    for (int c = lane; c < NB; c += 32) {
        unsigned long long k = sK[c];
#pragma unroll
        for (int j = 0; j < RROWS; j++)
            rr[j] += (k < kb[j]);
    }

#pragma unroll
    for (int j = 0; j < RROWS; j++) {
#pragma unroll
        for (int off = 16; off > 0; off >>= 1)
            rr[j] += __shfl_xor_sync(FULL, rr[j], off);
    }

    if (lane == 0) {
#pragma unroll
        for (int j = 0; j < RROWS; j++) {
            g_slab[rr[j]] = __uint_as_float((unsigned)(kb[j] >> 13));
            g_sidx[rr[j]] = base + j;
        }
    }
}

// ------------- Main kernel: SMEM-staged 1-D stencil over sorted rows --------
__global__ void __launch_bounds__(MT, 2) nest_main_kernel(
    const float* __restrict__ S, float* __restrict__ out)
{
    extern __shared__ char smem[];
    float4* sS   = (float4*)(smem + OFF_SS);    // [STAGE][NDF4]
    float*  sW   = (float*)(smem + OFF_SW);     // [TOUT][16] stencil weights
    float*  sRed = (float*)(smem + OFF_RED);    // [8 warps][8 rows][4]
    int*    sSrc = (int*)(smem + OFF_SRC);      // [STAGE]

    const int tid  = threadIdx.x;
    const int wid  = tid >> 5;
    const int lane = tid & 31;
    const int r0   = blockIdx.x * TOUT;

    // ---- stage source row ids ----
    if (tid < STAGE) {
        int p = r0 - HALO + tid;
        sSrc[tid] = (p >= 0 && p < NB) ? g_sidx[p] : -1;
    }
    __syncthreads();

    // ---- stage 46 rows into smem (zero-fill out-of-range halo) ----
    const float4* Sf4 = (const float4*)S;
    for (int i = tid; i < STAGE * NDF4; i += MT) {
        int j = i >> 7;                 // NDF4 == 128
        int c = i & (NDF4 - 1);
        int src = sSrc[j];
        sS[i] = (src >= 0) ? Sf4[(size_t)src * NDF4 + c]
                           : make_float4(0.f, 0.f, 0.f, 0.f);
    }

    // ---- weight table: warp wid handles rows wid*4 .. wid*4+3 ----
#pragma unroll
    for (int q4 = 0; q4 < 4; q4++) {
        const int rloc = wid * 4 + q4;
        const int r    = r0 + rloc;
        const int p    = r - HALO + lane;
        const bool valid = (lane < 15) && (p >= 0) && (p < NB);

        float lab = valid ? g_slab[p] : 0.0f;
        float Lb  = __shfl_sync(FULL, lab, HALO);         // lane 7 == self
        float d   = valid ? fabsf(lab - Lb) : INFINITY;

        int rank = 0;
#pragma unroll
        for (int src = 0; src < 15; src++) {
            float od = __shfl_sync(FULL, d, src);
            rank += (od < d) | ((od == d) & (src < lane));
        }
        bool sel = (rank < NK) && (lane < 15);
        float e  = sel ? __expf(-d * d * (1.0f / 50.0f)) : 0.0f;  // 2*STD^2=50

        float wsum = e;
#pragma unroll
        for (int off = 16; off > 0; off >>= 1)
            wsum += __shfl_xor_sync(FULL, wsum, off);

        if (lane < 16)
            sW[rloc * 16 + lane] = (lane < 15) ? e / wsum : 0.0f;
    }
    __syncthreads();

    // ---- source-iterated stencil ----
    // warp pair (wid>>1) owns 8 output rows; warp parity picks column half.
    const int rg    = wid >> 1;
    const int R0    = rg * 8;
    const int cbase = (wid & 1) * 32 + lane;

    float dotA[8], nxA[8], nmA[8];
#pragma unroll
    for (int q = 0; q < 8; q++) { dotA[q] = 0.f; nxA[q] = 0.f; nmA[q] = 0.f; }

#pragma unroll 1
    for (int sl = 0; sl < 2; sl++) {
        const int c = cbase + sl * 64;

        float4 m[8];
#pragma unroll
        for (int q = 0; q < 8; q++) m[q] = make_float4(0.f, 0.f, 0.f, 0.f);

#pragma unroll 11
        for (int t = 0; t < 22; t++) {              // staged slots R0..R0+21
            float4 s = sS[(R0 + t) * NDF4 + c];
#pragma unroll
            for (int q = 0; q < 8; q++) {
                const int o = t - q;                 // window offset
                if (o >= 0 && o <= 14) {             // compile-time pruned
                    float wq = sW[(R0 + q) * 16 + o];
                    m[q].x = fmaf(wq, s.x, m[q].x);
                    m[q].y = fmaf(wq, s.y, m[q].y);
                    m[q].z = fmaf(wq, s.z, m[q].z);
                    m[q].w = fmaf(wq, s.w, m[q].w);
                }
            }
        }

#pragma unroll
        for (int q = 0; q < 8; q++) {
            float4 x = sS[(R0 + q + HALO) * NDF4 + c];   // self row
            dotA[q] += x.x * m[q].x + x.y * m[q].y + x.z * m[q].z + x.w * m[q].w;
            nxA[q]  += x.x * x.x + x.y * x.y + x.z * x.z + x.w * x.w;
            nmA[q]  += m[q].x * m[q].x + m[q].y * m[q].y
                     + m[q].z * m[q].z + m[q].w * m[q].w;
        }
    }

    // ---- warp reduce 8x3 partials, park in smem ----
#pragma unroll
    for (int q = 0; q < 8; q++) {
#pragma unroll
        for (int off = 16; off > 0; off >>= 1) {
            dotA[q] += __shfl_xor_sync(FULL, dotA[q], off);
            nxA[q]  += __shfl_xor_sync(FULL, nxA[q],  off);
            nmA[q]  += __shfl_xor_sync(FULL, nmA[q],  off);
        }
    }
    if (lane == 0) {
#pragma unroll
        for (int q = 0; q < 8; q++) {
            sRed[(wid * 8 + q) * 4 + 0] = dotA[q];
            sRed[(wid * 8 + q) * 4 + 1] = nxA[q];
            sRed[(wid * 8 + q) * 4 + 2] = nmA[q];
        }
    }
    __syncthreads();

    // ---- warp 0: combine warp pairs, compute 32 sims, block-sum ----
    if (wid == 0) {
        const int rg2 = lane >> 3;
        const int q   = lane & 7;
        const int a   = ((2 * rg2)     * 8 + q) * 4;
        const int b2  = ((2 * rg2 + 1) * 8 + q) * 4;
        float dt = sRed[a + 0] + sRed[b2 + 0];
        float nx = sRed[a + 1] + sRed[b2 + 1];
        float nm = sRed[a + 2] + sRed[b2 + 2];
        float sim = dt / ((1e-10f + sqrtf(nx)) * (1e-10f + sqrtf(nm)));

#pragma unroll
        for (int off = 16; off > 0; off >>= 1)
            sim += __shfl_xor_sync(FULL, sim, off);

        if (lane == 0) {
            atomicAdd(&g_acc, (double)sim);
            __threadfence();
            int old = atomicAdd(&g_done, 1);
            if (old == MBLK - 1) {                  // last block finalizes
                double total = *((volatile double*)&g_acc);
                out[0] = (float)(1.0 - total / (double)NB);
                g_done = 0;                         // reset for graph replay
            }
        }
    }
}

extern "C" void kernel_launch(void* const* d_in, const int* in_sizes, int n_in,
                              void* d_out, int out_size)
{
    const float* S = (const float*)d_in[0];   // Struct [8192, 512]
    const float* L = (const float*)d_in[1];   // Label  [8192]
    float* out = (float*)d_out;

    (void)cudaFuncSetAttribute(nest_main_kernel,
                               cudaFuncAttributeMaxDynamicSharedMemorySize,
                               SMEM_SZ);

    nest_rank_kernel<<<RBLK, RT>>>(L);
    nest_main_kernel<<<MBLK, MT, SMEM_SZ>>>(S, out);
}

// round 12
// speedup vs baseline: 2.5967x; 1.3915x over previous
#include <cuda_runtime.h>
#include <math.h>

#define NB    8192
#define ND    512
#define NK    8
#define FULL  0xffffffffu

#define THREADS 256
#define WARPS   (THREADS / 32)
#define NBLK    (NB / WARPS)

// ---- sort kernel geometry ----
#define ST    1024
#define NBKT  8192
#define SORT_SMEM (NB * 8 * 2 + NBKT * 4 * 2 + 64 * 4)   // 196864 B

__device__ double g_acc;
__device__ int    g_done = 0;
__device__ float  g_slab[NB];   // labels in sorted order
__device__ int    g_sidx[NB];   // original row per sorted position

// -------- Sort kernel: single-block exact bucket sort on packed u64 keys ----
// key = label_bits<<13 | idx  (labels nonneg -> uint order == float order;
// idx makes keys unique). bucket = floor(v*8192) is monotone in v, so
// (bucket asc, key asc within bucket) == global key order. Repair pass
// insertion-sorts the (rare) multi-element buckets -> exact permutation.
__global__ void __launch_bounds__(ST) nest_sort_kernel(const float* __restrict__ L)
{
    extern __shared__ char sm[];
    unsigned long long* sKey  = (unsigned long long*)sm;          // [NB]
    unsigned long long* sOut  = sKey + NB;                        // [NB]
    int*                sHist = (int*)(sOut + NB);                // [NBKT]
    int*                sCur  = sHist + NBKT;                     // [NBKT]
    int*                sWarp = sCur + NBKT;                      // [64]

    const int tid  = threadIdx.x;
    const int lane = tid & 31;
    const int wid  = tid >> 5;

    if (tid == 0) g_acc = 0.0;

    for (int i = tid; i < NBKT; i += ST) sHist[i] = 0;
    __syncthreads();

    // load labels, build keys, histogram
    for (int i = tid; i < NB; i += ST) {
        float v = L[i];
        sKey[i] = ((unsigned long long)__float_as_uint(v) << 13) | (unsigned)i;
        int b = (int)(v * (float)NBKT);
        b = max(0, min(b, NBKT - 1));
        atomicAdd(&sHist[b], 1);
    }
    __syncthreads();

    // exclusive prefix sum over NBKT counters (8 per thread + block scan)
    const int base = tid * 8;
    int local[8];
    int sum = 0;
#pragma unroll
    for (int j = 0; j < 8; j++) { local[j] = sum; sum += sHist[base + j]; }

    int v = sum;                                   // inclusive scan of sums
#pragma unroll
    for (int off = 1; off < 32; off <<= 1) {
        int o = __shfl_up_sync(FULL, v, off);
        if (lane >= off) v += o;
    }
    if (lane == 31) sWarp[wid] = v;                // warp totals
    __syncthreads();
    if (wid == 0) {
        int wv = sWarp[lane];                      // 32 warps
#pragma unroll
        for (int off = 1; off < 32; off <<= 1) {
            int o = __shfl_up_sync(FULL, wv, off);
            if (lane >= off) wv += o;
        }
        sWarp[lane] = wv;                          // inclusive across warps
    }
    __syncthreads();
    const int warpBase = (wid > 0) ? sWarp[wid - 1] : 0;
    const int myExcl   = warpBase + v - sum;
#pragma unroll
    for (int j = 0; j < 8; j++) {
        int s = myExcl + local[j];
        sHist[base + j] = s;                       // bucket start (preserved)
        sCur[base + j]  = s;                       // cursor
    }
    __syncthreads();

    // scatter into bucket slots (arbitrary order within bucket)
    for (int i = tid; i < NB; i += ST) {
        unsigned long long k = sKey[i];
        float val = __uint_as_float((unsigned)(k >> 13));
        int b = max(0, min((int)(val * (float)NBKT), NBKT - 1));
        int pos = atomicAdd(&sCur[b], 1);
        sOut[pos] = k;
    }
    __syncthreads();

    // repair: insertion sort inside each bucket segment (tiny, mostly <=1)
    for (int b = tid; b < NBKT; b += ST) {
        int st = sHist[b];
        int en = sCur[b];
        for (int i = st + 1; i < en; i++) {
            unsigned long long key = sOut[i];
            int j = i - 1;
            while (j >= st && sOut[j] > key) { sOut[j + 1] = sOut[j]; j--; }
            sOut[j + 1] = key;
        }
    }
    __syncthreads();

    // emit sorted label / original index
    for (int r = tid; r < NB; r += ST) {
        unsigned long long k = sOut[r];
        g_slab[r] = __uint_as_float((unsigned)(k >> 13));
        g_sidx[r] = (int)(k & 0x1FFFu);
    }
}

// ------------- Main kernel (R8, known good): warp per sorted row ------------
__global__ void __launch_bounds__(THREADS) nest_main_kernel(
    const float* __restrict__ S, float* __restrict__ out)
{
    __shared__ double sSim[WARPS];

    const int tid  = threadIdx.x;
    const int wid  = tid >> 5;
    const int lane = tid & 31;

    const int r  = blockIdx.x * WARPS + wid;    // sorted position
    const float Lb = g_slab[r];
    const int   b  = g_sidx[r];                 // original row

    // two-pointer nearest-8 over the sorted window (broadcast loads)
    int   gidx[NK];
    float w[NK];
    gidx[0] = b; w[0] = 1.0f;
    float wsum = 1.0f;

    int lo = r - 1, hi = r + 1;
#pragma unroll
    for (int k = 1; k < NK; k++) {
        float dl = (lo >= 0) ? Lb - g_slab[lo] : INFINITY;
        float dh = (hi < NB) ? g_slab[hi] - Lb : INFINITY;
        float d; int gi;
        if (dl <= dh) { gi = g_sidx[lo]; d = dl; lo--; }
        else          { gi = g_sidx[hi]; d = dh; hi++; }
        gidx[k] = gi;
        float e = __expf(-d * d * (1.0f / 50.0f));   // 2*STD^2 = 50
        w[k] = e; wsum += e;
    }

    const float winv = 1.0f / wsum;
#pragma unroll
    for (int k = 0; k < NK; k++) w[k] *= winv;

    // fused gather + weighted mean + cosine terms
    const float4* xr = (const float4*)(S + (size_t)b * ND);
    float4 x[4];
#pragma unroll
    for (int t = 0; t < 4; t++) x[t] = xr[lane + t * 32];

    float dot = 0.0f, nx = 0.0f, nm = 0.0f;

#pragma unroll
    for (int t = 0; t < 4; t++) {
        int col = lane + t * 32;
        float mx = 0.0f, my = 0.0f, mz = 0.0f, mw = 0.0f;
#pragma unroll
        for (int k = 0; k < NK; k++) {
            float4 s = ((const float4*)(S + (size_t)gidx[k] * ND))[col];
            mx = fmaf(w[k], s.x, mx);
            my = fmaf(w[k], s.y, my);
            mz = fmaf(w[k], s.z, mz);
            mw = fmaf(w[k], s.w, mw);
        }
        dot += x[t].x * mx + x[t].y * my + x[t].z * mz + x[t].w * mw;
        nx  += x[t].x * x[t].x + x[t].y * x[t].y + x[t].z * x[t].z + x[t].w * x[t].w;
        nm  += mx * mx + my * my + mz * mz + mw * mw;
    }

#pragma unroll
    for (int off = 16; off > 0; off >>= 1) {
        dot += __shfl_xor_sync(FULL, dot, off);
        nx  += __shfl_xor_sync(FULL, nx,  off);
        nm  += __shfl_xor_sync(FULL, nm,  off);
    }

    if (lane == 0) {
        float sim = dot / ((1e-10f + sqrtf(nx)) * (1e-10f + sqrtf(nm)));
        sSim[wid] = (double)sim;
    }
    __syncthreads();

    if (tid == 0) {
        double bs = 0.0;
#pragma unroll
        for (int k = 0; k < WARPS; k++) bs += sSim[k];
        atomicAdd(&g_acc, bs);
        __threadfence();
        int old = atomicAdd(&g_done, 1);
        if (old == NBLK - 1) {                  // last block finalizes
            double total = *((volatile double*)&g_acc);
            out[0] = (float)(1.0 - total / (double)NB);
            g_done = 0;                         // reset for graph replay
        }
    }
}

extern "C" void kernel_launch(void* const* d_in, const int* in_sizes, int n_in,
                              void* d_out, int out_size)
{
    const float* S = (const float*)d_in[0];   // Struct [8192, 512]
    const float* L = (const float*)d_in[1];   // Label  [8192]
    float* out = (float*)d_out;

    (void)cudaFuncSetAttribute(nest_sort_kernel,
                               cudaFuncAttributeMaxDynamicSharedMemorySize,
                               SORT_SMEM);

    nest_sort_kernel<<<1, ST, SORT_SMEM>>>(L);
    nest_main_kernel<<<NBLK, THREADS>>>(S, out);
}